// round 9
// baseline (speedup 1.0000x reference)
#include <cuda_runtime.h>
#include <math.h>

#define NPTS    16384               // 8 * 2048 points per cloud
#define DIM     48                  // cells per axis
#define DIM2    (DIM * DIM)
#define NCELLS  (DIM * DIM * DIM)   // 110592
#define ORG     (-6.0f)
#define H       0.25f
#define INVH    4.0f
#define SCAN_T  1024
#define CPT     (NCELLS / SCAN_T)   // 108 cells per scan thread (27 int4)
#define SPAD    (NCELLS + 4)        // padded row: keeps row 1 16B-aligned
#define KMAX    4                   // shell cap; unresolved -> brute phase

__device__ float4 g_sorted[2][NPTS];        // cell-sorted points
__device__ int    g_count [2][NCELLS];
__device__ int    g_start [2][SPAD];        // [NCELLS] = sentinel (NPTS)
__device__ int    g_cursor[2][NCELLS];
__device__ int    g_cellid[2][NPTS];
__device__ int    g_pending[2 * NPTS];      // unresolved query ids
__device__ int    g_pcount;

__device__ __forceinline__ int cell_coord(float v) {
    int c = (int)floorf((v - ORG) * INVH);
    return min(DIM - 1, max(0, c));
}

// Distance from in-cell fraction f to the slab at cell offset o.
__device__ __forceinline__ float slab(int o, float f) {
    if (o > 0) return (float)o * H - f;
    if (o < 0) return f - (float)(o + 1) * H;
    return 0.0f;
}

// ---------------------------------------------------------------- K0: zero
__global__ void zero_kernel(float* __restrict__ out) {
    int i = blockIdx.x * blockDim.x + threadIdx.x;
    if (i == 0) { out[0] = 0.0f; g_pcount = 0; }
    if (i < NCELLS / 4) {
        reinterpret_cast<int4*>(g_count[0])[i] = make_int4(0, 0, 0, 0);
        reinterpret_cast<int4*>(g_count[1])[i] = make_int4(0, 0, 0, 0);
    }
}

// ------------------------------------------------------------ K1: histogram
__global__ void hist_kernel(const float* __restrict__ pc1,
                            const float* __restrict__ pc2) {
    int i = blockIdx.x * blockDim.x + threadIdx.x;
    if (i >= 2 * NPTS) return;
    int c = (i >= NPTS) ? 1 : 0;
    int j = i - c * NPTS;
    const float* pc = c ? pc2 : pc1;
    float x = pc[3 * j + 0], y = pc[3 * j + 1], z = pc[3 * j + 2];
    int cell = (cell_coord(z) * DIM + cell_coord(y)) * DIM + cell_coord(x);
    g_cellid[c][j] = cell;
    atomicAdd(&g_count[c][cell], 1);
}

// ------------------------------------------------- K2: scan (1 block/cloud)
__global__ void __launch_bounds__(SCAN_T)
scan_kernel() {
    const int c = blockIdx.x;
    const int t = threadIdx.x;
    __shared__ int sm[SCAN_T];

    const int4* __restrict__ cnt4 =
        reinterpret_cast<const int4*>(g_count[c]) + t * (CPT / 4);

    int4 v[CPT / 4];
    int local = 0;
    #pragma unroll
    for (int i = 0; i < CPT / 4; ++i) {
        v[i] = cnt4[i];
        local += v[i].x + v[i].y + v[i].z + v[i].w;
    }
    sm[t] = local;
    __syncthreads();

    #pragma unroll
    for (int off = 1; off < SCAN_T; off <<= 1) {
        int u = (t >= off) ? sm[t - off] : 0;
        __syncthreads();
        sm[t] += u;
        __syncthreads();
    }

    int run = sm[t] - local;
    int4* __restrict__ st4 = reinterpret_cast<int4*>(g_start[c])  + t * (CPT / 4);
    int4* __restrict__ cu4 = reinterpret_cast<int4*>(g_cursor[c]) + t * (CPT / 4);
    #pragma unroll
    for (int i = 0; i < CPT / 4; ++i) {
        int4 s;
        s.x = run;            run += v[i].x;
        s.y = run;            run += v[i].y;
        s.z = run;            run += v[i].z;
        s.w = run;            run += v[i].w;
        st4[i] = s;
        cu4[i] = s;
    }
    if (t == SCAN_T - 1) g_start[c][NCELLS] = NPTS;
}

// -------------------------------------------------------------- K3: scatter
__global__ void scatter_kernel(const float* __restrict__ pc1,
                               const float* __restrict__ pc2) {
    int i = blockIdx.x * blockDim.x + threadIdx.x;
    if (i >= 2 * NPTS) return;
    int c = (i >= NPTS) ? 1 : 0;
    int j = i - c * NPTS;
    const float* pc = c ? pc2 : pc1;
    float x = pc[3 * j + 0], y = pc[3 * j + 1], z = pc[3 * j + 2];
    int cell = g_cellid[c][j];
    int pos = atomicAdd(&g_cursor[c][cell], 1);
    g_sorted[c][pos] = make_float4(x, y, z, 0.0f);
}

// Scan cells [c0, c1] (contiguous span); points split stride-32 over the warp.
__device__ __forceinline__ void scan_span32(const float4* __restrict__ tgt,
                                            const int* __restrict__ cst,
                                            int c0, int c1, int lane,
                                            float qx, float qy, float qz,
                                            float& best2) {
    const int s = cst[c0];             // warp-uniform -> broadcast load
    const int e = cst[c1 + 1];
    for (int p = s + lane; p < e; p += 32) {
        const float4 b = tgt[p];
        const float dx = qx - b.x;
        const float dy = qy - b.y;
        const float dz = qz - b.z;
        const float d2 = fmaf(dx, dx, fmaf(dy, dy, dz * dz));
        best2 = fminf(best2, d2);
    }
}

__device__ __forceinline__ float warp_min(float v) {
    #pragma unroll
    for (int off = 16; off > 0; off >>= 1)
        v = fminf(v, __shfl_xor_sync(0xFFFFFFFFu, v, off));
    return v;
}

// --------------- K4: warp-per-query expanding-shell NN (phase A)
// One warp per query. Rows walked warp-uniform; points split stride-32.
// Per-row slab-distance culling uses the round-start reduced best2 (gate),
// so cull decisions are warp-uniform (no partial-mask span scans).
__global__ void __launch_bounds__(256)
query_kernel(float* __restrict__ out) {
    const int gw   = (blockIdx.x * blockDim.x + threadIdx.x) >> 5;  // 0..32767
    const int lane = threadIdx.x & 31;
    const int dir  = gw >> 14;
    const int qi   = gw & (NPTS - 1);
    const int tc   = dir ^ 1;

    const float4 q = g_sorted[dir][qi];
    const int cx = cell_coord(q.x);
    const int cy = cell_coord(q.y);
    const int cz = cell_coord(q.z);
    const float fx = q.x - (ORG + (float)cx * H);   // in-cell fraction
    const float fy = q.y - (ORG + (float)cy * H);
    const float fz = q.z - (ORG + (float)cz * H);
    // Margin for the sharp stopping bound (conservative if f out of [0,H)).
    const float mfr = fmaxf(0.0f,
        fminf(fminf(fminf(fx, H - fx), fminf(fy, H - fy)),
              fminf(fz, H - fz)));

    const float4* __restrict__ tgt = g_sorted[tc];
    const int*    __restrict__ cst = g_start[tc];

    float best2 = 3.0e38f;

    // ---- Own cell first.
    const int cc = (cz * DIM + cy) * DIM + cx;
    scan_span32(tgt, cst, cc, cc, lane, q.x, q.y, q.z, best2);
    best2 = warp_min(best2);

    // ---- Rest of box(1) with slab culling (gate = warp-uniform snapshot).
    {
        const float gate = best2;
        // x-neighbors of own cell.
        if (cx - 1 >= 0 && fx * fx < gate)
            scan_span32(tgt, cst, cc - 1, cc - 1, lane, q.x, q.y, q.z, best2);
        if (cx + 1 < DIM && (H - fx) * (H - fx) < gate)
            scan_span32(tgt, cst, cc + 1, cc + 1, lane, q.x, q.y, q.z, best2);
        // 8 rows with (oy, oz) != (0, 0).
        const int x0 = max(cx - 1, 0), x1 = min(cx + 1, DIM - 1);
        #pragma unroll
        for (int oz = -1; oz <= 1; ++oz) {
            const int z = cz + oz;
            if (z < 0 || z >= DIM) continue;
            const float dz = slab(oz, fz);
            #pragma unroll
            for (int oy = -1; oy <= 1; ++oy) {
                if ((oz | oy) == 0) continue;
                const int y = cy + oy;
                if (y < 0 || y >= DIM) continue;
                const float dy = slab(oy, fy);
                const float r2 = dz * dz + dy * dy;
                if (r2 >= gate) continue;
                const int rb = z * DIM2 + y * DIM;
                scan_span32(tgt, cst, rb + x0, rb + x1, lane,
                            q.x, q.y, q.z, best2);
            }
        }
        best2 = warp_min(best2);
    }

    // ---- Expand shells (capped at KMAX) with sharp bound + row culling.
    int k = 1;
    float bound = (float)k * H + mfr;
    while (best2 > bound * bound && k < KMAX) {
        ++k;
        const float gate = best2;
        const int z0 = max(cz - k, 0), z1 = min(cz + k, DIM - 1);
        const int y0 = max(cy - k, 0), y1 = min(cy + k, DIM - 1);
        const int xl = cx - k, xr = cx + k;
        const int xs = max(xl, 0), xe = min(xr, DIM - 1);
        const float dxl = fx + (float)(k - 1) * H;   // slab(-k, fx)
        const float dxr = (float)k * H - fx;         // slab(+k, fx)
        for (int z = z0; z <= z1; ++z) {
            const int oz = z - cz;
            const float dz = slab(oz, fz);
            const float dz2 = dz * dz;
            if (dz2 >= gate) continue;
            const bool zface = (oz == -k) || (oz == k);
            for (int y = y0; y <= y1; ++y) {
                const int oy = y - cy;
                const float dy = slab(oy, fy);
                const float r2 = dz2 + dy * dy;
                if (r2 >= gate) continue;
                const int rb = z * DIM2 + y * DIM;
                if (zface || (oy == -k) || (oy == k)) {
                    scan_span32(tgt, cst, rb + xs, rb + xe, lane,
                                q.x, q.y, q.z, best2);
                } else {
                    if (xl >= 0 && r2 + dxl * dxl < gate)
                        scan_span32(tgt, cst, rb + xl, rb + xl, lane,
                                    q.x, q.y, q.z, best2);
                    if (xr <= DIM - 1 && r2 + dxr * dxr < gate)
                        scan_span32(tgt, cst, rb + xr, rb + xr, lane,
                                    q.x, q.y, q.z, best2);
                }
            }
        }
        best2 = warp_min(best2);
        bound = (float)k * H + mfr;
    }

    const bool resolved = best2 <= bound * bound;

    float d = 0.0f;
    if (lane == 0) {
        if (resolved) {
            d = sqrtf(fmaxf(best2, 0.0f));
        } else {
            int idx = atomicAdd(&g_pcount, 1);
            g_pending[idx] = gw;
        }
    }

    // Block reduction: one query result per warp (on lane 0).
    __shared__ float warp_sums[8];
    if (lane == 0) warp_sums[threadIdx.x >> 5] = d;
    __syncthreads();
    if (threadIdx.x < 32) {
        float s = (lane < 8) ? warp_sums[lane] : 0.0f;
        #pragma unroll
        for (int off = 4; off > 0; off >>= 1)
            s += __shfl_xor_sync(0xFFFFFFFFu, s, off);
        if (lane == 0)
            atomicAdd(out, s * (1.0f / (float)NPTS));
    }
}

// ------------------- K5: brute-force for unresolved queries (phase B)
__global__ void __launch_bounds__(256)
brute_kernel(float* __restrict__ out) {
    const int gw   = (blockIdx.x * blockDim.x + threadIdx.x) >> 5;
    const int lane = threadIdx.x & 31;
    const int nw   = (gridDim.x * blockDim.x) >> 5;
    const int n    = g_pcount;

    for (int w = gw; w < n; w += nw) {
        const int gq  = g_pending[w];
        const int dir = gq >> 14;
        const int qi  = gq & (NPTS - 1);
        const float4 q = g_sorted[dir][qi];
        const float4* __restrict__ tgt = g_sorted[dir ^ 1];

        float best2 = 3.0e38f;
        for (int p = lane; p < NPTS; p += 32) {
            const float4 b = tgt[p];
            const float dx = q.x - b.x;
            const float dy = q.y - b.y;
            const float dz = q.z - b.z;
            const float d2 = fmaf(dx, dx, fmaf(dy, dy, dz * dz));
            best2 = fminf(best2, d2);
        }
        #pragma unroll
        for (int off = 16; off > 0; off >>= 1)
            best2 = fminf(best2, __shfl_xor_sync(0xFFFFFFFFu, best2, off));
        if (lane == 0)
            atomicAdd(out, sqrtf(fmaxf(best2, 0.0f)) * (1.0f / (float)NPTS));
    }
}

extern "C" void kernel_launch(void* const* d_in, const int* in_sizes, int n_in,
                              void* d_out, int out_size) {
    const float* pc1 = (const float*)d_in[0];
    const float* pc2 = (const float*)d_in[1];
    float* out = (float*)d_out;

    zero_kernel   <<<(NCELLS / 4 + 255) / 256, 256>>>(out);
    hist_kernel   <<<(2 * NPTS + 255) / 256, 256>>>(pc1, pc2);
    scan_kernel   <<<2, SCAN_T>>>();
    scatter_kernel<<<(2 * NPTS + 255) / 256, 256>>>(pc1, pc2);
    query_kernel  <<<(2 * NPTS * 32) / 256, 256>>>(out);
    brute_kernel  <<<64, 256>>>(out);
}

// round 10
// speedup vs baseline: 1.1354x; 1.1354x over previous
#include <cuda_runtime.h>
#include <math.h>

#define NPTS    16384               // 8 * 2048 points per cloud
#define DIM     48                  // cells per axis
#define DIM2    (DIM * DIM)
#define NCELLS  (DIM * DIM * DIM)   // 110592
#define ORG     (-6.0f)
#define H       0.25f
#define INVH    4.0f
#define SCAN_T  1024
#define CPT     (NCELLS / SCAN_T)   // 108 cells per scan thread (27 int4)
#define SPAD    (NCELLS + 4)        // padded row: keeps row 1 16B-aligned
#define KMAX    4                   // shell cap; unresolved -> brute phase

__device__ float4 g_sorted[2][NPTS];        // cell-sorted points
__device__ int    g_count [2][NCELLS];
__device__ int    g_start [2][SPAD];        // [NCELLS] = sentinel (NPTS)
__device__ int    g_cursor[2][NCELLS];
__device__ int    g_cellid[2][NPTS];
__device__ int    g_pending[2 * NPTS];      // unresolved query ids
__device__ int    g_pcount;

__device__ __forceinline__ int cell_coord(float v) {
    int c = (int)floorf((v - ORG) * INVH);
    return min(DIM - 1, max(0, c));
}

// Distance from in-cell fraction f to the slab at cell offset o.
__device__ __forceinline__ float slab(int o, float f) {
    if (o > 0) return (float)o * H - f;
    if (o < 0) return f - (float)(o + 1) * H;
    return 0.0f;
}

// ---------------------------------------------------------------- K0: zero
__global__ void zero_kernel(float* __restrict__ out) {
    int i = blockIdx.x * blockDim.x + threadIdx.x;
    if (i == 0) { out[0] = 0.0f; g_pcount = 0; }
    if (i < NCELLS / 4) {
        reinterpret_cast<int4*>(g_count[0])[i] = make_int4(0, 0, 0, 0);
        reinterpret_cast<int4*>(g_count[1])[i] = make_int4(0, 0, 0, 0);
    }
}

// ------------------------------------------------------------ K1: histogram
__global__ void hist_kernel(const float* __restrict__ pc1,
                            const float* __restrict__ pc2) {
    int i = blockIdx.x * blockDim.x + threadIdx.x;
    if (i >= 2 * NPTS) return;
    int c = (i >= NPTS) ? 1 : 0;
    int j = i - c * NPTS;
    const float* pc = c ? pc2 : pc1;
    float x = pc[3 * j + 0], y = pc[3 * j + 1], z = pc[3 * j + 2];
    int cell = (cell_coord(z) * DIM + cell_coord(y)) * DIM + cell_coord(x);
    g_cellid[c][j] = cell;
    atomicAdd(&g_count[c][cell], 1);
}

// ------------------------------------------------- K2: scan (1 block/cloud)
__global__ void __launch_bounds__(SCAN_T)
scan_kernel() {
    const int c = blockIdx.x;
    const int t = threadIdx.x;
    __shared__ int sm[SCAN_T];

    const int4* __restrict__ cnt4 =
        reinterpret_cast<const int4*>(g_count[c]) + t * (CPT / 4);

    int4 v[CPT / 4];
    int local = 0;
    #pragma unroll
    for (int i = 0; i < CPT / 4; ++i) {
        v[i] = cnt4[i];
        local += v[i].x + v[i].y + v[i].z + v[i].w;
    }
    sm[t] = local;
    __syncthreads();

    #pragma unroll
    for (int off = 1; off < SCAN_T; off <<= 1) {
        int u = (t >= off) ? sm[t - off] : 0;
        __syncthreads();
        sm[t] += u;
        __syncthreads();
    }

    int run = sm[t] - local;
    int4* __restrict__ st4 = reinterpret_cast<int4*>(g_start[c])  + t * (CPT / 4);
    int4* __restrict__ cu4 = reinterpret_cast<int4*>(g_cursor[c]) + t * (CPT / 4);
    #pragma unroll
    for (int i = 0; i < CPT / 4; ++i) {
        int4 s;
        s.x = run;            run += v[i].x;
        s.y = run;            run += v[i].y;
        s.z = run;            run += v[i].z;
        s.w = run;            run += v[i].w;
        st4[i] = s;
        cu4[i] = s;
    }
    if (t == SCAN_T - 1) g_start[c][NCELLS] = NPTS;
}

// -------------------------------------------------------------- K3: scatter
__global__ void scatter_kernel(const float* __restrict__ pc1,
                               const float* __restrict__ pc2) {
    int i = blockIdx.x * blockDim.x + threadIdx.x;
    if (i >= 2 * NPTS) return;
    int c = (i >= NPTS) ? 1 : 0;
    int j = i - c * NPTS;
    const float* pc = c ? pc2 : pc1;
    float x = pc[3 * j + 0], y = pc[3 * j + 1], z = pc[3 * j + 2];
    int cell = g_cellid[c][j];
    int pos = atomicAdd(&g_cursor[c][cell], 1);
    g_sorted[c][pos] = make_float4(x, y, z, 0.0f);
}

// Scan cells [c0, c1]; points split stride-4 over the quad.
__device__ __forceinline__ void scan_q4(const float4* __restrict__ tgt,
                                        const int* __restrict__ cst,
                                        int c0, int c1, int sub,
                                        float qx, float qy, float qz,
                                        float& best2) {
    const int s = cst[c0];
    const int e = cst[c1 + 1];
    for (int p = s + sub; p < e; p += 4) {
        const float4 b = tgt[p];
        const float dx = qx - b.x;
        const float dy = qy - b.y;
        const float dz = qz - b.z;
        const float d2 = fmaf(dx, dx, fmaf(dy, dy, dz * dz));
        best2 = fminf(best2, d2);
    }
}

// --------- K4: quad-cooperative expanding-shell NN w/ slab culling (phase A)
__global__ void __launch_bounds__(256)
query_kernel(float* __restrict__ out) {
    const int t    = blockIdx.x * blockDim.x + threadIdx.x;  // 0 .. 131071
    const int sub  = t & 3;
    const int gq   = t >> 2;            // 0 .. 32767
    const int dir  = gq >> 14;
    const int qi   = gq & (NPTS - 1);
    const int tc   = dir ^ 1;
    const unsigned qmask = 0xFu << (threadIdx.x & 28);

    const float4 q = g_sorted[dir][qi];
    const int cx = cell_coord(q.x);
    const int cy = cell_coord(q.y);
    const int cz = cell_coord(q.z);
    const float fx = q.x - (ORG + (float)cx * H);   // in-cell fraction
    const float fy = q.y - (ORG + (float)cy * H);
    const float fz = q.z - (ORG + (float)cz * H);
    // Margin for the sharp stopping bound (conservative if f out of [0,H)).
    const float mfr = fmaxf(0.0f,
        fminf(fminf(fminf(fx, H - fx), fminf(fy, H - fy)),
              fminf(fz, H - fz)));

    const float4* __restrict__ tgt = g_sorted[tc];
    const int*    __restrict__ cst = g_start[tc];

    float best2 = 3.0e38f;

    // ---- Own cell first (tight gate).
    const int cc = (cz * DIM + cy) * DIM + cx;
    scan_q4(tgt, cst, cc, cc, sub, q.x, q.y, q.z, best2);
    best2 = fminf(best2, __shfl_xor_sync(qmask, best2, 1));
    best2 = fminf(best2, __shfl_xor_sync(qmask, best2, 2));

    // ---- Rest of box(1), slab-culled against the gate (quad-uniform).
    {
        const float gate = best2;
        if (cx - 1 >= 0 && fx * fx < gate)
            scan_q4(tgt, cst, cc - 1, cc - 1, sub, q.x, q.y, q.z, best2);
        if (cx + 1 < DIM && (H - fx) * (H - fx) < gate)
            scan_q4(tgt, cst, cc + 1, cc + 1, sub, q.x, q.y, q.z, best2);
        const int x0 = max(cx - 1, 0), x1 = min(cx + 1, DIM - 1);
        #pragma unroll
        for (int oz = -1; oz <= 1; ++oz) {
            const int z = cz + oz;
            if (z < 0 || z >= DIM) continue;
            const float dz = slab(oz, fz);
            #pragma unroll
            for (int oy = -1; oy <= 1; ++oy) {
                if ((oz | oy) == 0) continue;
                const int y = cy + oy;
                if (y < 0 || y >= DIM) continue;
                const float dy = slab(oy, fy);
                const float r2 = fmaf(dz, dz, dy * dy);
                if (r2 >= gate) continue;
                const int rb = z * DIM2 + y * DIM;
                scan_q4(tgt, cst, rb + x0, rb + x1, sub, q.x, q.y, q.z, best2);
            }
        }
        best2 = fminf(best2, __shfl_xor_sync(qmask, best2, 1));
        best2 = fminf(best2, __shfl_xor_sync(qmask, best2, 2));
    }

    // ---- Expand shells (capped) with sharp bound + row culling.
    int k = 1;
    float bound = (float)k * H + mfr;
    while (best2 > bound * bound && k < KMAX) {
        ++k;
        const float gate = best2;
        const int z0 = max(cz - k, 0), z1 = min(cz + k, DIM - 1);
        const int y0 = max(cy - k, 0), y1 = min(cy + k, DIM - 1);
        const int xl = cx - k, xr = cx + k;
        const int xs = max(xl, 0), xe = min(xr, DIM - 1);
        const float dxl = fx + (float)(k - 1) * H;   // slab(-k, fx)
        const float dxr = (float)k * H - fx;         // slab(+k, fx)
        for (int z = z0; z <= z1; ++z) {
            const int oz = z - cz;
            const float dzs = slab(oz, fz);
            const float dz2 = dzs * dzs;
            if (dz2 >= gate) continue;
            const bool zface = (oz == -k) || (oz == k);
            for (int y = y0; y <= y1; ++y) {
                const int oy = y - cy;
                const float dys = slab(oy, fy);
                const float r2 = fmaf(dys, dys, dz2);
                if (r2 >= gate) continue;
                const int rb = z * DIM2 + y * DIM;
                if (zface || (oy == -k) || (oy == k)) {
                    scan_q4(tgt, cst, rb + xs, rb + xe, sub,
                            q.x, q.y, q.z, best2);
                } else {
                    if (xl >= 0 && fmaf(dxl, dxl, r2) < gate)
                        scan_q4(tgt, cst, rb + xl, rb + xl, sub,
                                q.x, q.y, q.z, best2);
                    if (xr <= DIM - 1 && fmaf(dxr, dxr, r2) < gate)
                        scan_q4(tgt, cst, rb + xr, rb + xr, sub,
                                q.x, q.y, q.z, best2);
                }
            }
        }
        best2 = fminf(best2, __shfl_xor_sync(qmask, best2, 1));
        best2 = fminf(best2, __shfl_xor_sync(qmask, best2, 2));
        bound = (float)k * H + mfr;
    }

    const bool resolved = best2 <= bound * bound;

    float d = 0.0f;
    if (sub == 0) {
        if (resolved) {
            d = sqrtf(fmaxf(best2, 0.0f));
        } else {
            int idx = atomicAdd(&g_pcount, 1);
            g_pending[idx] = gq;
        }
    }

    // Block reduction (256 threads = 8 warps), one atomicAdd per block.
    __shared__ float warp_sums[8];
    float v = d;
    #pragma unroll
    for (int off = 16; off > 0; off >>= 1)
        v += __shfl_xor_sync(0xFFFFFFFFu, v, off);
    const int lane = threadIdx.x & 31;
    const int wid  = threadIdx.x >> 5;
    if (lane == 0) warp_sums[wid] = v;
    __syncthreads();
    if (wid == 0) {
        float s = (lane < 8) ? warp_sums[lane] : 0.0f;
        #pragma unroll
        for (int off = 4; off > 0; off >>= 1)
            s += __shfl_xor_sync(0xFFFFFFFFu, s, off);
        if (lane == 0)
            atomicAdd(out, s * (1.0f / (float)NPTS));
    }
}

// ------------------- K5: brute-force for unresolved queries (phase B)
__global__ void __launch_bounds__(256)
brute_kernel(float* __restrict__ out) {
    const int gw   = (blockIdx.x * blockDim.x + threadIdx.x) >> 5;
    const int lane = threadIdx.x & 31;
    const int nw   = (gridDim.x * blockDim.x) >> 5;
    const int n    = g_pcount;

    for (int w = gw; w < n; w += nw) {
        const int gq  = g_pending[w];
        const int dir = gq >> 14;
        const int qi  = gq & (NPTS - 1);
        const float4 q = g_sorted[dir][qi];
        const float4* __restrict__ tgt = g_sorted[dir ^ 1];

        float best2 = 3.0e38f;
        for (int p = lane; p < NPTS; p += 32) {
            const float4 b = tgt[p];
            const float dx = q.x - b.x;
            const float dy = q.y - b.y;
            const float dz = q.z - b.z;
            const float d2 = fmaf(dx, dx, fmaf(dy, dy, dz * dz));
            best2 = fminf(best2, d2);
        }
        #pragma unroll
        for (int off = 16; off > 0; off >>= 1)
            best2 = fminf(best2, __shfl_xor_sync(0xFFFFFFFFu, best2, off));
        if (lane == 0)
            atomicAdd(out, sqrtf(fmaxf(best2, 0.0f)) * (1.0f / (float)NPTS));
    }
}

extern "C" void kernel_launch(void* const* d_in, const int* in_sizes, int n_in,
                              void* d_out, int out_size) {
    const float* pc1 = (const float*)d_in[0];
    const float* pc2 = (const float*)d_in[1];
    float* out = (float*)d_out;

    zero_kernel   <<<(NCELLS / 4 + 255) / 256, 256>>>(out);
    hist_kernel   <<<(2 * NPTS + 255) / 256, 256>>>(pc1, pc2);
    scan_kernel   <<<2, SCAN_T>>>();
    scatter_kernel<<<(2 * NPTS + 255) / 256, 256>>>(pc1, pc2);
    query_kernel  <<<(2 * NPTS * 4) / 256, 256>>>(out);
    brute_kernel  <<<64, 256>>>(out);
}